// round 2
// baseline (speedup 1.0000x reference)
#include <cuda_runtime.h>

// AdaptiveMemory: out[row] = coefM * mem[vids[row]] + coefH * h_last[row]
//   alpha = sigmoid(dot(h_last[row], W_alpha) + b_alpha)
//   coefM = d + (1-d)*alpha ; coefH = (1-d)*(1-alpha)
// B = 4096 rows, D = 1024. One CTA per row, 256 threads, float4 per thread.
// vids is int32 (JAX x64-disabled downcasts the reference's int64 arange).

#define D_DIM 1024
#define THREADS 256

__global__ __launch_bounds__(THREADS, 8)
void adaptive_memory_kernel(const float* __restrict__ h_last,
                            const int* __restrict__ vids,
                            const float* __restrict__ mem,
                            const float* __restrict__ W_alpha,
                            const float* __restrict__ b_alpha,
                            const float* __restrict__ medium_decay,
                            float* __restrict__ out,
                            int n_mem_rows) {
    const int row = blockIdx.x;
    const int tid = threadIdx.x;

    const float4* h4 = reinterpret_cast<const float4*>(h_last + (size_t)row * D_DIM);
    const float4* w4 = reinterpret_cast<const float4*>(W_alpha);

    // Load h chunk (reused for dot + blend) and kick off the gather load early
    // so its DRAM latency hides under the block reduction.
    float4 hv = h4[tid];

    int vid = vids[row];
    // Defensive clamp: a bad index becomes a wrong answer (diagnosable via
    // rel_err) rather than an illegal access.
    if (vid < 0) vid = 0;
    if (vid >= n_mem_rows) vid = n_mem_rows - 1;

    const float4* m4 = reinterpret_cast<const float4*>(mem + (size_t)vid * D_DIM);
    float4 mv = m4[tid];

    float4 wv = w4[tid];
    float p = hv.x * wv.x + hv.y * wv.y + hv.z * wv.z + hv.w * wv.w;

    // Warp reduce
    #pragma unroll
    for (int off = 16; off > 0; off >>= 1)
        p += __shfl_xor_sync(0xFFFFFFFFu, p, off);

    __shared__ float warp_sums[THREADS / 32];
    __shared__ float s_coefM, s_coefH;

    const int warp = tid >> 5;
    const int lane = tid & 31;
    if (lane == 0) warp_sums[warp] = p;
    __syncthreads();

    if (tid == 0) {
        float sum = b_alpha[0];
        #pragma unroll
        for (int i = 0; i < THREADS / 32; i++) sum += warp_sums[i];
        float alpha = 1.0f / (1.0f + __expf(-sum));
        float d = medium_decay[0];
        s_coefM = d + (1.0f - d) * alpha;
        s_coefH = (1.0f - d) * (1.0f - alpha);
    }
    __syncthreads();

    const float cM = s_coefM;
    const float cH = s_coefH;

    float4 o;
    o.x = cM * mv.x + cH * hv.x;
    o.y = cM * mv.y + cH * hv.y;
    o.z = cM * mv.z + cH * hv.z;
    o.w = cM * mv.w + cH * hv.w;

    reinterpret_cast<float4*>(out + (size_t)row * D_DIM)[tid] = o;
}

extern "C" void kernel_launch(void* const* d_in, const int* in_sizes, int n_in,
                              void* d_out, int out_size) {
    const float* h_last       = (const float*)d_in[0];
    const int*   vids         = (const int*)d_in[1];
    const float* mem          = (const float*)d_in[2];
    const float* W_alpha      = (const float*)d_in[3];
    const float* b_alpha      = (const float*)d_in[4];
    const float* medium_decay = (const float*)d_in[5];
    float*       out          = (float*)d_out;

    const int B          = in_sizes[0] / D_DIM;  // 4096
    const int n_mem_rows = in_sizes[2] / D_DIM;  // 100000

    adaptive_memory_kernel<<<B, THREADS>>>(h_last, vids, mem, W_alpha,
                                           b_alpha, medium_decay, out,
                                           n_mem_rows);
}

// round 3
// speedup vs baseline: 1.2007x; 1.2007x over previous
#include <cuda_runtime.h>

// AdaptiveMemory: out[row] = coefM * mem[vids[row]] + coefH * h_last[row]
//   alpha = sigmoid(dot(h_last[row], W_alpha) + b_alpha)
//   coefM = d + (1-d)*alpha ; coefH = (1-d)*(1-alpha)
// B = 4096 rows, D = 1024.
// One WARP per row: no __syncthreads, no smem, pure shfl butterfly reduce.
// Each lane owns 8 float4 chunks (lane + 32*j), fully coalesced.

#define D_DIM   1024
#define CHUNKS  8            // (D/4) / 32 lanes
#define THREADS 256          // 8 warps = 8 rows per block

__global__ __launch_bounds__(THREADS, 2)
void adaptive_memory_kernel(const float* __restrict__ h_last,
                            const int* __restrict__ vids,
                            const float* __restrict__ mem,
                            const float* __restrict__ W_alpha,
                            const float* __restrict__ b_alpha,
                            const float* __restrict__ medium_decay,
                            float* __restrict__ out,
                            int n_mem_rows) {
    const int warp = threadIdx.x >> 5;
    const int lane = threadIdx.x & 31;
    const int row  = blockIdx.x * (THREADS / 32) + warp;

    const float4* h4 = reinterpret_cast<const float4*>(h_last + (size_t)row * D_DIM);
    const float4* w4 = reinterpret_cast<const float4*>(W_alpha);

    int vid = vids[row];
    if (vid < 0) vid = 0;
    if (vid >= n_mem_rows) vid = n_mem_rows - 1;
    const float4* m4 = reinterpret_cast<const float4*>(mem + (size_t)vid * D_DIM);

    // Front-batch all DRAM loads for maximum MLP: 16 outstanding LDG.128/thread.
    float4 hv[CHUNKS], mv[CHUNKS];
    #pragma unroll
    for (int j = 0; j < CHUNKS; j++) hv[j] = h4[lane + 32 * j];
    #pragma unroll
    for (int j = 0; j < CHUNKS; j++) mv[j] = m4[lane + 32 * j];

    // Dot product with W (L1/L2-resident after first wave).
    float p = 0.0f;
    #pragma unroll
    for (int j = 0; j < CHUNKS; j++) {
        float4 wv = w4[lane + 32 * j];
        p += hv[j].x * wv.x + hv[j].y * wv.y + hv[j].z * wv.z + hv[j].w * wv.w;
    }

    // Butterfly reduce: every lane ends with the full sum (no broadcast needed).
    #pragma unroll
    for (int off = 16; off > 0; off >>= 1)
        p += __shfl_xor_sync(0xFFFFFFFFu, p, off);

    const float sum   = p + b_alpha[0];
    const float alpha = 1.0f / (1.0f + __expf(-sum));
    const float d     = medium_decay[0];
    const float cM    = d + (1.0f - d) * alpha;
    const float cH    = (1.0f - d) * (1.0f - alpha);

    float4* o4 = reinterpret_cast<float4*>(out + (size_t)row * D_DIM);
    #pragma unroll
    for (int j = 0; j < CHUNKS; j++) {
        float4 o;
        o.x = cM * mv[j].x + cH * hv[j].x;
        o.y = cM * mv[j].y + cH * hv[j].y;
        o.z = cM * mv[j].z + cH * hv[j].z;
        o.w = cM * mv[j].w + cH * hv[j].w;
        o4[lane + 32 * j] = o;
    }
}

extern "C" void kernel_launch(void* const* d_in, const int* in_sizes, int n_in,
                              void* d_out, int out_size) {
    const float* h_last       = (const float*)d_in[0];
    const int*   vids         = (const int*)d_in[1];
    const float* mem          = (const float*)d_in[2];
    const float* W_alpha      = (const float*)d_in[3];
    const float* b_alpha      = (const float*)d_in[4];
    const float* medium_decay = (const float*)d_in[5];
    float*       out          = (float*)d_out;

    const int B          = in_sizes[0] / D_DIM;  // 4096
    const int n_mem_rows = in_sizes[2] / D_DIM;  // 100000

    const int rows_per_block = THREADS / 32;
    adaptive_memory_kernel<<<B / rows_per_block, THREADS>>>(
        h_last, vids, mem, W_alpha, b_alpha, medium_decay, out, n_mem_rows);
}